// round 3
// baseline (speedup 1.0000x reference)
#include <cuda_runtime.h>
#include <cuda_bf16.h>
#include <math_constants.h>

// Problem constants (fixed by the dataset)
#define MAXN 50000
#define MAXE 800000
#define MAXT (MAXE + MAXN)   // edges + self loops
#define IN1 128
#define H1  8
#define C1  32
#define D1  (H1 * C1)        // 256
#define D2  64

#define NEG_SLOPE 0.2f
#define EPS 1e-16f

// ---------------- scratch (device globals; no allocation allowed) -----------
__device__ int   g_is64;            // 1 if edge_index buffer is int64, else 0
__device__ int   g_src[MAXE];
__device__ int   g_dst[MAXE];
__device__ int   g_cnt[MAXN];
__device__ int   g_offs[MAXN + 1];
__device__ int   g_cursor[MAXN];
__device__ int   g_srcs[MAXT];
__device__ float g_h1[(size_t)MAXN * D1];
__device__ float g_out1[(size_t)MAXN * D1];
__device__ float g_h2[(size_t)MAXN * D2];
__device__ float g_a1s[MAXN * H1];
__device__ float g_a1d[MAXN * H1];
__device__ float g_a2s[MAXN];
__device__ float g_a2d[MAXN];

// ---------------- dtype probe + edge normalization --------------------------
// If the buffer holds int64 little-endian values < 2^31, every odd 32-bit word
// is zero. If it holds int32 node ids, odd words are random ids (OR != 0).
__global__ void detect_kernel(const unsigned int* __restrict__ w, int nwords) {
    __shared__ unsigned int s_or[256];
    unsigned int acc = 0;
    int limit = nwords < 2048 ? nwords : 2048;
    for (int i = 1 + 2 * threadIdx.x; i < limit; i += 2 * blockDim.x)
        acc |= w[i];
    s_or[threadIdx.x] = acc;
    __syncthreads();
    for (int s = 128; s > 0; s >>= 1) {
        if (threadIdx.x < s) s_or[threadIdx.x] |= s_or[threadIdx.x + s];
        __syncthreads();
    }
    if (threadIdx.x == 0) g_is64 = (s_or[0] == 0u) ? 1 : 0;
}

__global__ void normalize_kernel(const unsigned int* __restrict__ w, int E) {
    int e = blockIdx.x * blockDim.x + threadIdx.x;
    if (e >= E) return;
    int s, d;
    if (g_is64) {                 // int64 layout: words [0,2E) src, [2E,4E) dst
        s = (int)w[2 * e];
        d = (int)w[2 * (size_t)E + 2 * e];
    } else {                      // int32 layout: words [0,E) src, [E,2E) dst
        s = (int)w[e];
        d = (int)w[(size_t)E + e];
    }
    g_src[e] = s;
    g_dst[e] = d;
}

// ---------------- CSR build -------------------------------------------------
__global__ void init_cnt_kernel(int N) {
    int i = blockIdx.x * blockDim.x + threadIdx.x;
    if (i < N) g_cnt[i] = 1;  // self loop pre-counted
}

__global__ void hist_kernel(int E, int N) {
    int e = blockIdx.x * blockDim.x + threadIdx.x;
    if (e < E) {
        int dst = g_dst[e];
        if ((unsigned)dst < (unsigned)N) atomicAdd(&g_cnt[dst], 1);
    }
}

// single-block exclusive scan over g_cnt -> g_offs (and g_cursor copy)
__global__ void scan_kernel(int n) {
    __shared__ int warp_sums[32];
    __shared__ int s_carry;
    int tid = threadIdx.x;
    int lane = tid & 31, wid = tid >> 5;
    if (tid == 0) s_carry = 0;
    __syncthreads();
    for (int base = 0; base < n; base += 1024) {
        int i = base + tid;
        int v = (i < n) ? g_cnt[i] : 0;
        int x = v;
        #pragma unroll
        for (int o = 1; o < 32; o <<= 1) {
            int y = __shfl_up_sync(0xffffffffu, x, o);
            if (lane >= o) x += y;
        }
        if (lane == 31) warp_sums[wid] = x;
        __syncthreads();
        if (wid == 0) {
            int w = warp_sums[lane];
            #pragma unroll
            for (int o = 1; o < 32; o <<= 1) {
                int y = __shfl_up_sync(0xffffffffu, w, o);
                if (lane >= o) w += y;
            }
            warp_sums[lane] = w;
        }
        __syncthreads();
        int excl = x - v + (wid > 0 ? warp_sums[wid - 1] : 0);
        int carry = s_carry;
        if (i < n) {
            int off = carry + excl;
            g_offs[i]   = off;
            g_cursor[i] = off;
        }
        __syncthreads();
        if (tid == 1023) s_carry = carry + warp_sums[31];
        __syncthreads();
    }
    if (threadIdx.x == 0) g_offs[n] = s_carry;
}

__global__ void scatter_self_kernel(int N) {
    int i = blockIdx.x * blockDim.x + threadIdx.x;
    if (i < N) {
        int pos = atomicAdd(&g_cursor[i], 1);
        if ((unsigned)pos < (unsigned)MAXT) g_srcs[pos] = i;
    }
}

__global__ void scatter_edge_kernel(int E, int N) {
    int e = blockIdx.x * blockDim.x + threadIdx.x;
    if (e < E) {
        int src = g_src[e];
        int dst = g_dst[e];
        if ((unsigned)dst >= (unsigned)N || (unsigned)src >= (unsigned)N) return;
        int pos = atomicAdd(&g_cursor[dst], 1);
        if ((unsigned)pos < (unsigned)MAXT) g_srcs[pos] = src;
    }
}

// ---------------- GEMM: C[M,Ncols] = A[M,K] * B[K,Ncols] --------------------
// BM=64, BN=64, BK=16, TM=TN=4, 256 threads. A/C selected by flag.
__global__ void gemm_kernel(const float* __restrict__ Ain, const float* __restrict__ B,
                            int which,  // 0: A=Ain, C=g_h1 ; 1: A=g_out1, C=g_h2
                            int M, int K, int Ncols) {
    const int BM = 64, BN = 64, BK = 16, TM = 4, TN = 4;
    __shared__ float As[BK][BM + 4];
    __shared__ float Bs[BK][BN];

    const float* A = (which == 0) ? Ain : (const float*)g_out1;
    float*       C = (which == 0) ? g_h1 : g_h2;

    int t = threadIdx.x;
    int tx = t & 15;        // 0..15
    int ty = t >> 4;        // 0..15
    int row0 = blockIdx.x * BM;
    int col0 = blockIdx.y * BN;

    float acc[TM][TN];
    #pragma unroll
    for (int i = 0; i < TM; i++)
        #pragma unroll
        for (int j = 0; j < TN; j++) acc[i][j] = 0.0f;

    int aRow = t >> 2;            // 0..63
    int aCol = (t & 3) * 4;       // 0,4,8,12
    int bRow = t >> 4;            // 0..15
    int bCol = (t & 15) * 4;      // 0..60

    for (int k0 = 0; k0 < K; k0 += BK) {
        float4 av = make_float4(0.f, 0.f, 0.f, 0.f);
        int ar = row0 + aRow;
        if (ar < M) av = *(const float4*)&A[(size_t)ar * K + k0 + aCol];
        As[aCol + 0][aRow] = av.x;
        As[aCol + 1][aRow] = av.y;
        As[aCol + 2][aRow] = av.z;
        As[aCol + 3][aRow] = av.w;
        float4 bv = *(const float4*)&B[(size_t)(k0 + bRow) * Ncols + col0 + bCol];
        *(float4*)&Bs[bRow][bCol] = bv;
        __syncthreads();
        #pragma unroll
        for (int k = 0; k < BK; k++) {
            float ra[TM], rb[TN];
            #pragma unroll
            for (int i = 0; i < TM; i++) ra[i] = As[k][ty * TM + i];
            float4 b4 = *(const float4*)&Bs[k][tx * TN];
            rb[0] = b4.x; rb[1] = b4.y; rb[2] = b4.z; rb[3] = b4.w;
            #pragma unroll
            for (int i = 0; i < TM; i++)
                #pragma unroll
                for (int j = 0; j < TN; j++)
                    acc[i][j] = fmaf(ra[i], rb[j], acc[i][j]);
        }
        __syncthreads();
    }
    #pragma unroll
    for (int i = 0; i < TM; i++) {
        int r = row0 + ty * TM + i;
        if (r < M) {
            #pragma unroll
            for (int j = 0; j < TN; j++)
                C[(size_t)r * Ncols + col0 + tx * TN + j] = acc[i][j];
        }
    }
}

// ---------------- layer 1 attention logits ----------------------------------
__global__ void att1_kernel(const float* __restrict__ att_s,
                            const float* __restrict__ att_d, int N) {
    int n = blockIdx.x;
    if (n >= N) return;
    int t = threadIdx.x;
    int h = t >> 5, c = t & 31;
    float v = g_h1[(size_t)n * D1 + t];
    float ps = v * __ldg(&att_s[t]);
    float pd = v * __ldg(&att_d[t]);
    #pragma unroll
    for (int o = 16; o > 0; o >>= 1) {
        ps += __shfl_xor_sync(0xffffffffu, ps, o);
        pd += __shfl_xor_sync(0xffffffffu, pd, o);
    }
    if (c == 0) {
        g_a1s[n * H1 + h] = ps;
        g_a1d[n * H1 + h] = pd;
    }
}

// ---------------- layer 1 aggregation: warp per dst -------------------------
__global__ void agg1_kernel(const float* __restrict__ b1, int N) {
    int warp = (blockIdx.x * blockDim.x + threadIdx.x) >> 5;
    int lane = threadIdx.x & 31;
    if (warp >= N) return;
    int d = warp;
    int beg = g_offs[d], end = g_offs[d + 1];

    float ad[H1];
    #pragma unroll
    for (int h = 0; h < H1; h++) ad[h] = g_a1d[d * H1 + h];

    float m[H1];
    #pragma unroll
    for (int h = 0; h < H1; h++) m[h] = -CUDART_INF_F;
    for (int i = beg + lane; i < end; i += 32) {
        int s = g_srcs[i];
        #pragma unroll
        for (int h = 0; h < H1; h++) {
            float e = g_a1s[s * H1 + h] + ad[h];
            e = e > 0.0f ? e : NEG_SLOPE * e;
            m[h] = fmaxf(m[h], e);
        }
    }
    #pragma unroll
    for (int h = 0; h < H1; h++)
        #pragma unroll
        for (int o = 16; o > 0; o >>= 1)
            m[h] = fmaxf(m[h], __shfl_xor_sync(0xffffffffu, m[h], o));

    float acc[H1], ssum[H1];
    #pragma unroll
    for (int h = 0; h < H1; h++) { acc[h] = 0.0f; ssum[h] = 0.0f; }
    for (int i = beg; i < end; i++) {
        int s = g_srcs[i];  // uniform across warp -> broadcast
        const float* hrow = &g_h1[(size_t)s * D1];
        #pragma unroll
        for (int h = 0; h < H1; h++) {
            float e = g_a1s[s * H1 + h] + ad[h];
            e = e > 0.0f ? e : NEG_SLOPE * e;
            float ex = __expf(e - m[h]);
            ssum[h] += ex;
            acc[h] = fmaf(ex, hrow[h * C1 + lane], acc[h]);
        }
    }
    float* orow = &g_out1[(size_t)d * D1];
    #pragma unroll
    for (int h = 0; h < H1; h++) {
        float o = acc[h] / (ssum[h] + EPS) + __ldg(&b1[h * C1 + lane]);
        o = o > 0.0f ? o : (expm1f(o));  // elu
        orow[h * C1 + lane] = o;
    }
}

// ---------------- layer 2 attention logits (1 head, 64 ch) ------------------
__global__ void att2_kernel(const float* __restrict__ att_s,
                            const float* __restrict__ att_d, int N) {
    int warp = (blockIdx.x * blockDim.x + threadIdx.x) >> 5;
    int lane = threadIdx.x & 31;
    if (warp >= N) return;
    int n = warp;
    float v0 = g_h2[(size_t)n * D2 + lane];
    float v1 = g_h2[(size_t)n * D2 + 32 + lane];
    float ps = v0 * __ldg(&att_s[lane]) + v1 * __ldg(&att_s[32 + lane]);
    float pd = v0 * __ldg(&att_d[lane]) + v1 * __ldg(&att_d[32 + lane]);
    #pragma unroll
    for (int o = 16; o > 0; o >>= 1) {
        ps += __shfl_xor_sync(0xffffffffu, ps, o);
        pd += __shfl_xor_sync(0xffffffffu, pd, o);
    }
    if (lane == 0) { g_a2s[n] = ps; g_a2d[n] = pd; }
}

// ---------------- layer 2 aggregation: warp per dst -------------------------
__global__ void agg2_kernel(const float* __restrict__ b2,
                            float* __restrict__ out, int N) {
    int warp = (blockIdx.x * blockDim.x + threadIdx.x) >> 5;
    int lane = threadIdx.x & 31;
    if (warp >= N) return;
    int d = warp;
    int beg = g_offs[d], end = g_offs[d + 1];
    float ad = g_a2d[d];

    float m = -CUDART_INF_F;
    for (int i = beg + lane; i < end; i += 32) {
        int s = g_srcs[i];
        float e = g_a2s[s] + ad;
        e = e > 0.0f ? e : NEG_SLOPE * e;
        m = fmaxf(m, e);
    }
    #pragma unroll
    for (int o = 16; o > 0; o >>= 1)
        m = fmaxf(m, __shfl_xor_sync(0xffffffffu, m, o));

    float acc0 = 0.0f, acc1 = 0.0f, ssum = 0.0f;
    for (int i = beg; i < end; i++) {
        int s = g_srcs[i];
        float e = g_a2s[s] + ad;
        e = e > 0.0f ? e : NEG_SLOPE * e;
        float ex = __expf(e - m);
        ssum += ex;
        const float* hrow = &g_h2[(size_t)s * D2];
        acc0 = fmaf(ex, hrow[lane],      acc0);
        acc1 = fmaf(ex, hrow[32 + lane], acc1);
    }
    float inv = 1.0f / (ssum + EPS);
    out[(size_t)d * D2 + lane]      = acc0 * inv + __ldg(&b2[lane]);
    out[(size_t)d * D2 + 32 + lane] = acc1 * inv + __ldg(&b2[32 + lane]);
}

// ---------------- launch ----------------------------------------------------
extern "C" void kernel_launch(void* const* d_in, const int* in_sizes, int n_in,
                              void* d_out, int out_size) {
    const float* x    = (const float*)d_in[0];
    const unsigned int* edge_w = (const unsigned int*)d_in[1];
    const float* W1   = (const float*)d_in[2];
    const float* as1  = (const float*)d_in[3];
    const float* ad1  = (const float*)d_in[4];
    const float* b1   = (const float*)d_in[5];
    const float* W2   = (const float*)d_in[6];
    const float* as2  = (const float*)d_in[7];
    const float* ad2  = (const float*)d_in[8];
    const float* b2   = (const float*)d_in[9];
    float* out = (float*)d_out;

    int N = in_sizes[0] / IN1;
    int E = in_sizes[1] / 2;   // element count is 2*E under both int32/int64

    // dtype probe + edge normalization (int32 vs int64 buffer)
    detect_kernel<<<1, 256>>>(edge_w, 2 * E);
    normalize_kernel<<<(E + 255) / 256, 256>>>(edge_w, E);

    // CSR build (self loops folded in)
    init_cnt_kernel<<<(N + 255) / 256, 256>>>(N);
    hist_kernel<<<(E + 255) / 256, 256>>>(E, N);
    scan_kernel<<<1, 1024>>>(N);
    scatter_self_kernel<<<(N + 255) / 256, 256>>>(N);
    scatter_edge_kernel<<<(E + 255) / 256, 256>>>(E, N);

    // layer 1
    dim3 g1((N + 63) / 64, D1 / 64);
    gemm_kernel<<<g1, 256>>>(x, W1, /*which=*/0, N, IN1, D1);
    att1_kernel<<<N, 256>>>(as1, ad1, N);
    agg1_kernel<<<(N + 7) / 8, 256>>>(b1, N);

    // layer 2
    dim3 g2((N + 63) / 64, D2 / 64);
    gemm_kernel<<<g2, 256>>>(x /*unused*/, W2, /*which=*/1, N, D1, D2);
    att2_kernel<<<(N + 7) / 8, 256>>>(as2, ad2, N);
    agg2_kernel<<<(N + 7) / 8, 256>>>(b2, out, N);
}

// round 4
// speedup vs baseline: 1.1680x; 1.1680x over previous
#include <cuda_runtime.h>
#include <cuda_bf16.h>
#include <math_constants.h>

// Problem constants (fixed by the dataset)
#define MAXN 50000
#define MAXE 800000
#define MAXT (MAXE + MAXN)   // edges + self loops
#define IN1 128
#define H1  8
#define C1  32
#define D1  (H1 * C1)        // 256
#define D2  64

#define NEG_SLOPE 0.2f
#define EPS 1e-16f

// ---------------- scratch (device globals; no allocation allowed) -----------
__device__ int   g_is64;            // 1 if edge_index buffer is int64, else 0
__device__ int   g_src[MAXE];
__device__ int   g_dst[MAXE];
__device__ int   g_cnt[MAXN];
__device__ int   g_offs[MAXN + 1];
__device__ int   g_cursor[MAXN];
__device__ int   g_srcs[MAXT];
__device__ float g_h1[(size_t)MAXN * D1];
__device__ float g_out1[(size_t)MAXN * D1];
__device__ float g_h2[(size_t)MAXN * D2];
__device__ float g_a1s[MAXN * H1];
__device__ float g_a1d[MAXN * H1];
__device__ float g_a2s[MAXN];
__device__ float g_a2d[MAXN];

// ---------------- dtype probe ------------------------------------------------
__global__ void detect_kernel(const unsigned int* __restrict__ w, int nwords) {
    __shared__ unsigned int s_or[256];
    unsigned int acc = 0;
    int limit = nwords < 2048 ? nwords : 2048;
    for (int i = 1 + 2 * threadIdx.x; i < limit; i += 2 * blockDim.x)
        acc |= w[i];
    s_or[threadIdx.x] = acc;
    __syncthreads();
    for (int s = 128; s > 0; s >>= 1) {
        if (threadIdx.x < s) s_or[threadIdx.x] |= s_or[threadIdx.x + s];
        __syncthreads();
    }
    if (threadIdx.x == 0) g_is64 = (s_or[0] == 0u) ? 1 : 0;
}

__global__ void init_cnt_kernel(int N) {
    int i = blockIdx.x * blockDim.x + threadIdx.x;
    if (i < N) g_cnt[i] = 1;  // self loop pre-counted
}

// fused: normalize edge buffer (int32 or int64) into g_src/g_dst + histogram dst
__global__ void normalize_hist_kernel(const unsigned int* __restrict__ w, int E, int N) {
    int e = blockIdx.x * blockDim.x + threadIdx.x;
    if (e >= E) return;
    int s, d;
    if (g_is64) {                 // int64 layout: words [0,2E) src, [2E,4E) dst
        s = (int)w[2 * (size_t)e];
        d = (int)w[2 * (size_t)E + 2 * (size_t)e];
    } else {                      // int32 layout: words [0,E) src, [E,2E) dst
        s = (int)w[e];
        d = (int)w[(size_t)E + e];
    }
    g_src[e] = s;
    g_dst[e] = d;
    if ((unsigned)d < (unsigned)N) atomicAdd(&g_cnt[d], 1);
}

// single-block exclusive scan over g_cnt -> g_offs (and g_cursor copy)
__global__ void scan_kernel(int n) {
    __shared__ int warp_sums[32];
    __shared__ int s_carry;
    int tid = threadIdx.x;
    int lane = tid & 31, wid = tid >> 5;
    if (tid == 0) s_carry = 0;
    __syncthreads();
    for (int base = 0; base < n; base += 1024) {
        int i = base + tid;
        int v = (i < n) ? g_cnt[i] : 0;
        int x = v;
        #pragma unroll
        for (int o = 1; o < 32; o <<= 1) {
            int y = __shfl_up_sync(0xffffffffu, x, o);
            if (lane >= o) x += y;
        }
        if (lane == 31) warp_sums[wid] = x;
        __syncthreads();
        if (wid == 0) {
            int w = warp_sums[lane];
            #pragma unroll
            for (int o = 1; o < 32; o <<= 1) {
                int y = __shfl_up_sync(0xffffffffu, w, o);
                if (lane >= o) w += y;
            }
            warp_sums[lane] = w;
        }
        __syncthreads();
        int excl = x - v + (wid > 0 ? warp_sums[wid - 1] : 0);
        int carry = s_carry;
        if (i < n) {
            int off = carry + excl;
            g_offs[i]   = off;
            g_cursor[i] = off;
        }
        __syncthreads();
        if (tid == 1023) s_carry = carry + warp_sums[31];
        __syncthreads();
    }
    if (threadIdx.x == 0) g_offs[n] = s_carry;
}

__global__ void scatter_self_kernel(int N) {
    int i = blockIdx.x * blockDim.x + threadIdx.x;
    if (i < N) {
        int pos = atomicAdd(&g_cursor[i], 1);
        if ((unsigned)pos < (unsigned)MAXT) g_srcs[pos] = i;
    }
}

__global__ void scatter_edge_kernel(int E, int N) {
    int e = blockIdx.x * blockDim.x + threadIdx.x;
    if (e < E) {
        int src = g_src[e];
        int dst = g_dst[e];
        if ((unsigned)dst >= (unsigned)N || (unsigned)src >= (unsigned)N) return;
        int pos = atomicAdd(&g_cursor[dst], 1);
        if ((unsigned)pos < (unsigned)MAXT) g_srcs[pos] = src;
    }
}

// ---------------- tf32 tensor-core GEMM -------------------------------------
// C[M,Ncols] = A[M,K] * B[K,Ncols].  BM=128, BN=64, BK=32. 256 thr (8 warps).
// Warp grid 4(M) x 2(N); warp tile 32x32 = 2 mtiles x 4 ntiles of m16n8k8.
__device__ __forceinline__ unsigned f2tf(float f) {
    unsigned r;
    asm("cvt.rna.tf32.f32 %0, %1;" : "=r"(r) : "f"(f));
    return r;
}

__global__ void __launch_bounds__(256, 2)
gemm_tf32_kernel(const float* __restrict__ Ain, const float* __restrict__ B,
                 int which,  // 0: A=Ain, C=g_h1 ; 1: A=g_out1, C=g_h2
                 int M, int K, int Ncols) {
    const int BM = 128, BN = 64, BK = 32;
    __shared__ unsigned As[BK][BM + 8];   // +8 pad -> conflict-free frag loads
    __shared__ unsigned Bs[BK][BN + 8];

    const float* A = (which == 0) ? Ain : (const float*)g_out1;
    float*       C = (which == 0) ? g_h1 : g_h2;

    int tid  = threadIdx.x;
    int wid  = tid >> 5, lane = tid & 31;
    int wm   = wid & 3;        // 0..3  (M)
    int wn   = wid >> 2;       // 0..1  (N)
    int row0 = blockIdx.x * BM;
    int col0 = blockIdx.y * BN;

    int lg = lane >> 2;        // groupID 0..7
    int lt = lane & 3;         // thread-in-group 0..3

    float acc[2][4][4];
    #pragma unroll
    for (int i = 0; i < 2; i++)
        #pragma unroll
        for (int j = 0; j < 4; j++)
            #pragma unroll
            for (int r = 0; r < 4; r++) acc[i][j][r] = 0.0f;

    // global load mapping
    int arow = tid >> 1;              // 0..127
    int acol = (tid & 1) * 16;        // 0 / 16  (4 float4)
    int brow = tid >> 3;              // 0..31
    int bcol = (tid & 7) * 8;         // 2 float4

    for (int k0 = 0; k0 < K; k0 += BK) {
        // ---- load A tile (with M guard) ----
        int ar = row0 + arow;
        const float* ap = &A[(size_t)ar * K + k0 + acol];
        #pragma unroll
        for (int v = 0; v < 4; v++) {
            float4 av = (ar < M) ? *(const float4*)(ap + 4 * v)
                                 : make_float4(0.f, 0.f, 0.f, 0.f);
            As[acol + 4 * v + 0][arow] = f2tf(av.x);
            As[acol + 4 * v + 1][arow] = f2tf(av.y);
            As[acol + 4 * v + 2][arow] = f2tf(av.z);
            As[acol + 4 * v + 3][arow] = f2tf(av.w);
        }
        // ---- load B tile ----
        const float* bp = &B[(size_t)(k0 + brow) * Ncols + col0 + bcol];
        #pragma unroll
        for (int v = 0; v < 2; v++) {
            float4 bv = *(const float4*)(bp + 4 * v);
            Bs[brow][bcol + 4 * v + 0] = f2tf(bv.x);
            Bs[brow][bcol + 4 * v + 1] = f2tf(bv.y);
            Bs[brow][bcol + 4 * v + 2] = f2tf(bv.z);
            Bs[brow][bcol + 4 * v + 3] = f2tf(bv.w);
        }
        __syncthreads();

        #pragma unroll
        for (int kk = 0; kk < BK; kk += 8) {
            unsigned areg[2][4];
            #pragma unroll
            for (int mt = 0; mt < 2; mt++) {
                int r = wm * 32 + mt * 16 + lg;
                areg[mt][0] = As[kk + lt    ][r    ];
                areg[mt][1] = As[kk + lt    ][r + 8];
                areg[mt][2] = As[kk + lt + 4][r    ];
                areg[mt][3] = As[kk + lt + 4][r + 8];
            }
            unsigned breg[4][2];
            #pragma unroll
            for (int nt = 0; nt < 4; nt++) {
                int c = wn * 32 + nt * 8 + lg;
                breg[nt][0] = Bs[kk + lt    ][c];
                breg[nt][1] = Bs[kk + lt + 4][c];
            }
            #pragma unroll
            for (int mt = 0; mt < 2; mt++)
                #pragma unroll
                for (int nt = 0; nt < 4; nt++) {
                    asm volatile(
                        "mma.sync.aligned.m16n8k8.row.col.f32.tf32.tf32.f32 "
                        "{%0,%1,%2,%3}, {%4,%5,%6,%7}, {%8,%9}, {%0,%1,%2,%3};\n"
                        : "+f"(acc[mt][nt][0]), "+f"(acc[mt][nt][1]),
                          "+f"(acc[mt][nt][2]), "+f"(acc[mt][nt][3])
                        : "r"(areg[mt][0]), "r"(areg[mt][1]),
                          "r"(areg[mt][2]), "r"(areg[mt][3]),
                          "r"(breg[nt][0]), "r"(breg[nt][1]));
                }
        }
        __syncthreads();
    }

    // ---- epilogue ----
    #pragma unroll
    for (int mt = 0; mt < 2; mt++) {
        #pragma unroll
        for (int nt = 0; nt < 4; nt++) {
            int r = row0 + wm * 32 + mt * 16 + lg;
            int c = col0 + wn * 32 + nt * 8 + 2 * lt;
            if (r < M)
                *(float2*)&C[(size_t)r * Ncols + c] =
                    make_float2(acc[mt][nt][0], acc[mt][nt][1]);
            if (r + 8 < M)
                *(float2*)&C[(size_t)(r + 8) * Ncols + c] =
                    make_float2(acc[mt][nt][2], acc[mt][nt][3]);
        }
    }
}

// ---------------- layer 1 attention logits ----------------------------------
__global__ void att1_kernel(const float* __restrict__ att_s,
                            const float* __restrict__ att_d, int N) {
    int n = blockIdx.x;
    if (n >= N) return;
    int t = threadIdx.x;
    int h = t >> 5, c = t & 31;
    float v = g_h1[(size_t)n * D1 + t];
    float ps = v * __ldg(&att_s[t]);
    float pd = v * __ldg(&att_d[t]);
    #pragma unroll
    for (int o = 16; o > 0; o >>= 1) {
        ps += __shfl_xor_sync(0xffffffffu, ps, o);
        pd += __shfl_xor_sync(0xffffffffu, pd, o);
    }
    if (c == 0) {
        g_a1s[n * H1 + h] = ps;
        g_a1d[n * H1 + h] = pd;
    }
}

// ---------------- layer 1 aggregation: warp per dst -------------------------
__global__ void agg1_kernel(const float* __restrict__ b1, int N) {
    int warp = (blockIdx.x * blockDim.x + threadIdx.x) >> 5;
    int lane = threadIdx.x & 31;
    if (warp >= N) return;
    int d = warp;
    int beg = g_offs[d], end = g_offs[d + 1];

    float ad[H1];
    #pragma unroll
    for (int h = 0; h < H1; h++) ad[h] = g_a1d[d * H1 + h];

    float m[H1];
    #pragma unroll
    for (int h = 0; h < H1; h++) m[h] = -CUDART_INF_F;
    for (int i = beg + lane; i < end; i += 32) {
        int s = g_srcs[i];
        #pragma unroll
        for (int h = 0; h < H1; h++) {
            float e = g_a1s[s * H1 + h] + ad[h];
            e = e > 0.0f ? e : NEG_SLOPE * e;
            m[h] = fmaxf(m[h], e);
        }
    }
    #pragma unroll
    for (int h = 0; h < H1; h++)
        #pragma unroll
        for (int o = 16; o > 0; o >>= 1)
            m[h] = fmaxf(m[h], __shfl_xor_sync(0xffffffffu, m[h], o));

    float acc[H1], ssum[H1];
    #pragma unroll
    for (int h = 0; h < H1; h++) { acc[h] = 0.0f; ssum[h] = 0.0f; }
    for (int i = beg; i < end; i++) {
        int s = g_srcs[i];  // uniform across warp -> broadcast
        const float* hrow = &g_h1[(size_t)s * D1];
        #pragma unroll
        for (int h = 0; h < H1; h++) {
            float e = g_a1s[s * H1 + h] + ad[h];
            e = e > 0.0f ? e : NEG_SLOPE * e;
            float ex = __expf(e - m[h]);
            ssum[h] += ex;
            acc[h] = fmaf(ex, hrow[h * C1 + lane], acc[h]);
        }
    }
    float* orow = &g_out1[(size_t)d * D1];
    #pragma unroll
    for (int h = 0; h < H1; h++) {
        float o = acc[h] / (ssum[h] + EPS) + __ldg(&b1[h * C1 + lane]);
        o = o > 0.0f ? o : (expm1f(o));  // elu
        orow[h * C1 + lane] = o;
    }
}

// ---------------- layer 2 attention logits (1 head, 64 ch) ------------------
__global__ void att2_kernel(const float* __restrict__ att_s,
                            const float* __restrict__ att_d, int N) {
    int warp = (blockIdx.x * blockDim.x + threadIdx.x) >> 5;
    int lane = threadIdx.x & 31;
    if (warp >= N) return;
    int n = warp;
    float v0 = g_h2[(size_t)n * D2 + lane];
    float v1 = g_h2[(size_t)n * D2 + 32 + lane];
    float ps = v0 * __ldg(&att_s[lane]) + v1 * __ldg(&att_s[32 + lane]);
    float pd = v0 * __ldg(&att_d[lane]) + v1 * __ldg(&att_d[32 + lane]);
    #pragma unroll
    for (int o = 16; o > 0; o >>= 1) {
        ps += __shfl_xor_sync(0xffffffffu, ps, o);
        pd += __shfl_xor_sync(0xffffffffu, pd, o);
    }
    if (lane == 0) { g_a2s[n] = ps; g_a2d[n] = pd; }
}

// ---------------- layer 2 aggregation: warp per dst -------------------------
__global__ void agg2_kernel(const float* __restrict__ b2,
                            float* __restrict__ out, int N) {
    int warp = (blockIdx.x * blockDim.x + threadIdx.x) >> 5;
    int lane = threadIdx.x & 31;
    if (warp >= N) return;
    int d = warp;
    int beg = g_offs[d], end = g_offs[d + 1];
    float ad = g_a2d[d];

    float m = -CUDART_INF_F;
    for (int i = beg + lane; i < end; i += 32) {
        int s = g_srcs[i];
        float e = g_a2s[s] + ad;
        e = e > 0.0f ? e : NEG_SLOPE * e;
        m = fmaxf(m, e);
    }
    #pragma unroll
    for (int o = 16; o > 0; o >>= 1)
        m = fmaxf(m, __shfl_xor_sync(0xffffffffu, m, o));

    float acc0 = 0.0f, acc1 = 0.0f, ssum = 0.0f;
    for (int i = beg; i < end; i++) {
        int s = g_srcs[i];
        float e = g_a2s[s] + ad;
        e = e > 0.0f ? e : NEG_SLOPE * e;
        float ex = __expf(e - m);
        ssum += ex;
        const float* hrow = &g_h2[(size_t)s * D2];
        acc0 = fmaf(ex, hrow[lane],      acc0);
        acc1 = fmaf(ex, hrow[32 + lane], acc1);
    }
    float inv = 1.0f / (ssum + EPS);
    out[(size_t)d * D2 + lane]      = acc0 * inv + __ldg(&b2[lane]);
    out[(size_t)d * D2 + 32 + lane] = acc1 * inv + __ldg(&b2[32 + lane]);
}

// ---------------- launch ----------------------------------------------------
extern "C" void kernel_launch(void* const* d_in, const int* in_sizes, int n_in,
                              void* d_out, int out_size) {
    const float* x    = (const float*)d_in[0];
    const unsigned int* edge_w = (const unsigned int*)d_in[1];
    const float* W1   = (const float*)d_in[2];
    const float* as1  = (const float*)d_in[3];
    const float* ad1  = (const float*)d_in[4];
    const float* b1   = (const float*)d_in[5];
    const float* W2   = (const float*)d_in[6];
    const float* as2  = (const float*)d_in[7];
    const float* ad2  = (const float*)d_in[8];
    const float* b2   = (const float*)d_in[9];
    float* out = (float*)d_out;

    int N = in_sizes[0] / IN1;
    int E = in_sizes[1] / 2;   // element count is 2*E under both int32/int64

    // dtype probe + CSR build (self loops folded in)
    detect_kernel<<<1, 256>>>(edge_w, 2 * E);
    init_cnt_kernel<<<(N + 255) / 256, 256>>>(N);
    normalize_hist_kernel<<<(E + 255) / 256, 256>>>(edge_w, E, N);
    scan_kernel<<<1, 1024>>>(N);
    scatter_self_kernel<<<(N + 255) / 256, 256>>>(N);
    scatter_edge_kernel<<<(E + 255) / 256, 256>>>(E, N);

    // layer 1
    dim3 g1((N + 127) / 128, D1 / 64);
    gemm_tf32_kernel<<<g1, 256>>>(x, W1, /*which=*/0, N, IN1, D1);
    att1_kernel<<<N, 256>>>(as1, ad1, N);
    agg1_kernel<<<(N + 7) / 8, 256>>>(b1, N);

    // layer 2
    dim3 g2((N + 127) / 128, D2 / 64);
    gemm_tf32_kernel<<<g2, 256>>>(x /*unused*/, W2, /*which=*/1, N, D1, D2);
    att2_kernel<<<(N + 7) / 8, 256>>>(as2, ad2, N);
    agg2_kernel<<<(N + 7) / 8, 256>>>(b2, out, N);
}

// round 5
// speedup vs baseline: 1.4249x; 1.2200x over previous
#include <cuda_runtime.h>
#include <cuda_bf16.h>
#include <math_constants.h>

// Problem constants (fixed by the dataset)
#define MAXN 50000
#define MAXE 800000
#define MAXT (MAXE + MAXN)   // edges + self loops
#define IN1 128
#define H1  8
#define C1  32
#define D1  (H1 * C1)        // 256
#define D2  64
#define MAXB ((MAXN + 255) / 256)

#define NEG_SLOPE 0.2f
#define EPS 1e-16f

// ---------------- scratch (device globals; no allocation allowed) -----------
__device__ int   g_is64;
__device__ int   g_src[MAXE];
__device__ int   g_dst[MAXE];
__device__ int   g_cnt[MAXN];
__device__ int   g_offs[MAXN + 1];
__device__ int   g_cursor[MAXN];
__device__ int   g_bsum[MAXB + 1];
__device__ int   g_srcs[MAXT];
__device__ float g_h1[(size_t)MAXN * D1];
__device__ float g_out1[(size_t)MAXN * D1];
__device__ float g_h2[(size_t)MAXN * D2];
__device__ float g_a1s[MAXN * H1];
__device__ float g_a1d[MAXN * H1];
__device__ float g_a2s[MAXN];
__device__ float g_a2d[MAXN];

// ---------------- dtype probe ------------------------------------------------
__global__ void detect_kernel(const unsigned int* __restrict__ w, int nwords) {
    __shared__ unsigned int s_or[256];
    unsigned int acc = 0;
    int limit = nwords < 2048 ? nwords : 2048;
    for (int i = 1 + 2 * threadIdx.x; i < limit; i += 2 * blockDim.x)
        acc |= w[i];
    s_or[threadIdx.x] = acc;
    __syncthreads();
    for (int s = 128; s > 0; s >>= 1) {
        if (threadIdx.x < s) s_or[threadIdx.x] |= s_or[threadIdx.x + s];
        __syncthreads();
    }
    if (threadIdx.x == 0) g_is64 = (s_or[0] == 0u) ? 1 : 0;
}

__global__ void init_cnt_kernel(int N) {
    int i = blockIdx.x * blockDim.x + threadIdx.x;
    if (i < N) g_cnt[i] = 1;  // self loop pre-counted
}

// fused: normalize edge buffer (int32 or int64) into g_src/g_dst + histogram dst
__global__ void normalize_hist_kernel(const unsigned int* __restrict__ w, int E, int N) {
    int e = blockIdx.x * blockDim.x + threadIdx.x;
    if (e >= E) return;
    int s, d;
    if (g_is64) {
        s = (int)w[2 * (size_t)e];
        d = (int)w[2 * (size_t)E + 2 * (size_t)e];
    } else {
        s = (int)w[e];
        d = (int)w[(size_t)E + e];
    }
    g_src[e] = s;
    g_dst[e] = d;
    if ((unsigned)d < (unsigned)N) atomicAdd(&g_cnt[d], 1);
}

// ---------------- parallel 3-phase scan --------------------------------------
__global__ void scan_block_kernel(int n) {
    __shared__ int ws[8];
    int tid = threadIdx.x, lane = tid & 31, wid = tid >> 5;
    int i = blockIdx.x * 256 + tid;
    int v = (i < n) ? g_cnt[i] : 0;
    int x = v;
    #pragma unroll
    for (int o = 1; o < 32; o <<= 1) {
        int y = __shfl_up_sync(0xffffffffu, x, o);
        if (lane >= o) x += y;
    }
    if (lane == 31) ws[wid] = x;
    __syncthreads();
    if (wid == 0 && lane < 8) {
        int wv = ws[lane];
        #pragma unroll
        for (int o = 1; o < 8; o <<= 1) {
            int y = __shfl_up_sync(0x000000ffu, wv, o);
            if (lane >= o) wv += y;
        }
        ws[lane] = wv;
    }
    __syncthreads();
    int excl = x - v + (wid > 0 ? ws[wid - 1] : 0);
    if (i < n) g_offs[i] = excl;              // block-local exclusive
    if (tid == 255) g_bsum[blockIdx.x] = excl + v;  // block total
}

__global__ void scan_top_kernel(int nb) {
    // single block, up to 256 block sums -> exclusive scan in place
    __shared__ int ws[8];
    int tid = threadIdx.x, lane = tid & 31, wid = tid >> 5;
    int v = (tid < nb) ? g_bsum[tid] : 0;
    int x = v;
    #pragma unroll
    for (int o = 1; o < 32; o <<= 1) {
        int y = __shfl_up_sync(0xffffffffu, x, o);
        if (lane >= o) x += y;
    }
    if (lane == 31) ws[wid] = x;
    __syncthreads();
    if (wid == 0 && lane < 8) {
        int wv = ws[lane];
        #pragma unroll
        for (int o = 1; o < 8; o <<= 1) {
            int y = __shfl_up_sync(0x000000ffu, wv, o);
            if (lane >= o) wv += y;
        }
        ws[lane] = wv;
    }
    __syncthreads();
    int excl = x - v + (wid > 0 ? ws[wid - 1] : 0);
    if (tid < nb) g_bsum[tid] = excl;
}

__global__ void scan_add_kernel(int n) {
    int i = blockIdx.x * 256 + threadIdx.x;
    if (i < n) {
        int off = g_offs[i] + g_bsum[blockIdx.x];
        g_offs[i]   = off;
        g_cursor[i] = off;
        if (i == n - 1) g_offs[n] = off + g_cnt[i];
    }
}

__global__ void scatter_self_kernel(int N) {
    int i = blockIdx.x * blockDim.x + threadIdx.x;
    if (i < N) {
        int pos = atomicAdd(&g_cursor[i], 1);
        if ((unsigned)pos < (unsigned)MAXT) g_srcs[pos] = i;
    }
}

__global__ void scatter_edge_kernel(int E, int N) {
    int e = blockIdx.x * blockDim.x + threadIdx.x;
    if (e < E) {
        int src = g_src[e];
        int dst = g_dst[e];
        if ((unsigned)dst >= (unsigned)N || (unsigned)src >= (unsigned)N) return;
        int pos = atomicAdd(&g_cursor[dst], 1);
        if ((unsigned)pos < (unsigned)MAXT) g_srcs[pos] = src;
    }
}

// ---------------- tf32 tensor-core GEMM -------------------------------------
__device__ __forceinline__ unsigned f2tf(float f) {
    unsigned r;
    asm("cvt.rna.tf32.f32 %0, %1;" : "=r"(r) : "f"(f));
    return r;
}

__global__ void __launch_bounds__(256, 2)
gemm_tf32_kernel(const float* __restrict__ Ain, const float* __restrict__ B,
                 int which,  // 0: A=Ain, C=g_h1 ; 1: A=g_out1, C=g_h2
                 int M, int K, int Ncols) {
    const int BM = 128, BN = 64, BK = 32;
    __shared__ unsigned As[BK][BM + 8];
    __shared__ unsigned Bs[BK][BN + 8];

    const float* A = (which == 0) ? Ain : (const float*)g_out1;
    float*       C = (which == 0) ? g_h1 : g_h2;

    int tid  = threadIdx.x;
    int wid  = tid >> 5, lane = tid & 31;
    int wm   = wid & 3;
    int wn   = wid >> 2;
    int row0 = blockIdx.x * BM;
    int col0 = blockIdx.y * BN;

    int lg = lane >> 2;
    int lt = lane & 3;

    float acc[2][4][4];
    #pragma unroll
    for (int i = 0; i < 2; i++)
        #pragma unroll
        for (int j = 0; j < 4; j++)
            #pragma unroll
            for (int r = 0; r < 4; r++) acc[i][j][r] = 0.0f;

    int arow = tid >> 1;
    int acol = (tid & 1) * 16;
    int brow = tid >> 3;
    int bcol = (tid & 7) * 8;

    for (int k0 = 0; k0 < K; k0 += BK) {
        int ar = row0 + arow;
        const float* ap = &A[(size_t)ar * K + k0 + acol];
        #pragma unroll
        for (int v = 0; v < 4; v++) {
            float4 av = (ar < M) ? *(const float4*)(ap + 4 * v)
                                 : make_float4(0.f, 0.f, 0.f, 0.f);
            As[acol + 4 * v + 0][arow] = f2tf(av.x);
            As[acol + 4 * v + 1][arow] = f2tf(av.y);
            As[acol + 4 * v + 2][arow] = f2tf(av.z);
            As[acol + 4 * v + 3][arow] = f2tf(av.w);
        }
        const float* bp = &B[(size_t)(k0 + brow) * Ncols + col0 + bcol];
        #pragma unroll
        for (int v = 0; v < 2; v++) {
            float4 bv = *(const float4*)(bp + 4 * v);
            Bs[brow][bcol + 4 * v + 0] = f2tf(bv.x);
            Bs[brow][bcol + 4 * v + 1] = f2tf(bv.y);
            Bs[brow][bcol + 4 * v + 2] = f2tf(bv.z);
            Bs[brow][bcol + 4 * v + 3] = f2tf(bv.w);
        }
        __syncthreads();

        #pragma unroll
        for (int kk = 0; kk < BK; kk += 8) {
            unsigned areg[2][4];
            #pragma unroll
            for (int mt = 0; mt < 2; mt++) {
                int r = wm * 32 + mt * 16 + lg;
                areg[mt][0] = As[kk + lt    ][r    ];
                areg[mt][1] = As[kk + lt    ][r + 8];
                areg[mt][2] = As[kk + lt + 4][r    ];
                areg[mt][3] = As[kk + lt + 4][r + 8];
            }
            unsigned breg[4][2];
            #pragma unroll
            for (int nt = 0; nt < 4; nt++) {
                int c = wn * 32 + nt * 8 + lg;
                breg[nt][0] = Bs[kk + lt    ][c];
                breg[nt][1] = Bs[kk + lt + 4][c];
            }
            #pragma unroll
            for (int mt = 0; mt < 2; mt++)
                #pragma unroll
                for (int nt = 0; nt < 4; nt++) {
                    asm volatile(
                        "mma.sync.aligned.m16n8k8.row.col.f32.tf32.tf32.f32 "
                        "{%0,%1,%2,%3}, {%4,%5,%6,%7}, {%8,%9}, {%0,%1,%2,%3};\n"
                        : "+f"(acc[mt][nt][0]), "+f"(acc[mt][nt][1]),
                          "+f"(acc[mt][nt][2]), "+f"(acc[mt][nt][3])
                        : "r"(areg[mt][0]), "r"(areg[mt][1]),
                          "r"(areg[mt][2]), "r"(areg[mt][3]),
                          "r"(breg[nt][0]), "r"(breg[nt][1]));
                }
        }
        __syncthreads();
    }

    #pragma unroll
    for (int mt = 0; mt < 2; mt++) {
        #pragma unroll
        for (int nt = 0; nt < 4; nt++) {
            int r = row0 + wm * 32 + mt * 16 + lg;
            int c = col0 + wn * 32 + nt * 8 + 2 * lt;
            if (r < M)
                *(float2*)&C[(size_t)r * Ncols + c] =
                    make_float2(acc[mt][nt][0], acc[mt][nt][1]);
            if (r + 8 < M)
                *(float2*)&C[(size_t)(r + 8) * Ncols + c] =
                    make_float2(acc[mt][nt][2], acc[mt][nt][3]);
        }
    }
}

// ---------------- layer 1 attention logits ----------------------------------
__global__ void att1_kernel(const float* __restrict__ att_s,
                            const float* __restrict__ att_d, int N) {
    int n = blockIdx.x;
    if (n >= N) return;
    int t = threadIdx.x;
    int h = t >> 5, c = t & 31;
    float v = g_h1[(size_t)n * D1 + t];
    float ps = v * __ldg(&att_s[t]);
    float pd = v * __ldg(&att_d[t]);
    #pragma unroll
    for (int o = 16; o > 0; o >>= 1) {
        ps += __shfl_xor_sync(0xffffffffu, ps, o);
        pd += __shfl_xor_sync(0xffffffffu, pd, o);
    }
    if (c == 0) {
        g_a1s[n * H1 + h] = ps;
        g_a1d[n * H1 + h] = pd;
    }
}

// ---------------- layer 1 aggregation: 2 warps per dst (4 heads each) -------
__global__ void agg1_kernel(const float* __restrict__ b1, int N) {
    int gw   = (blockIdx.x * blockDim.x + threadIdx.x) >> 5;
    int lane = threadIdx.x & 31;
    int d    = gw >> 1;
    int half = gw & 1;
    if (d >= N) return;
    int hb = half * 4;          // head base: 0 or 4
    int beg = g_offs[d], end = g_offs[d + 1];

    float4 ad4 = *(const float4*)&g_a1d[d * H1 + hb];
    float ad[4] = {ad4.x, ad4.y, ad4.z, ad4.w};

    // pass 1: per-head max
    float m[4] = {-CUDART_INF_F, -CUDART_INF_F, -CUDART_INF_F, -CUDART_INF_F};
    for (int i = beg + lane; i < end; i += 32) {
        int s = g_srcs[i];
        float4 as4 = *(const float4*)&g_a1s[s * H1 + hb];
        float e0 = as4.x + ad[0]; e0 = e0 > 0.f ? e0 : NEG_SLOPE * e0;
        float e1 = as4.y + ad[1]; e1 = e1 > 0.f ? e1 : NEG_SLOPE * e1;
        float e2 = as4.z + ad[2]; e2 = e2 > 0.f ? e2 : NEG_SLOPE * e2;
        float e3 = as4.w + ad[3]; e3 = e3 > 0.f ? e3 : NEG_SLOPE * e3;
        m[0] = fmaxf(m[0], e0); m[1] = fmaxf(m[1], e1);
        m[2] = fmaxf(m[2], e2); m[3] = fmaxf(m[3], e3);
    }
    #pragma unroll
    for (int h = 0; h < 4; h++)
        #pragma unroll
        for (int o = 16; o > 0; o >>= 1)
            m[h] = fmaxf(m[h], __shfl_xor_sync(0xffffffffu, m[h], o));

    // pass 2: exp-weighted gather, unrolled by 2 for MLP
    float acc[4] = {0.f, 0.f, 0.f, 0.f};
    float ssum[4] = {0.f, 0.f, 0.f, 0.f};
    int i = beg;
    for (; i + 1 < end; i += 2) {
        int s0 = g_srcs[i], s1 = g_srcs[i + 1];
        float4 as0 = *(const float4*)&g_a1s[s0 * H1 + hb];
        float4 as1 = *(const float4*)&g_a1s[s1 * H1 + hb];
        const float* r0 = &g_h1[(size_t)s0 * D1 + hb * C1 + lane];
        const float* r1 = &g_h1[(size_t)s1 * D1 + hb * C1 + lane];
        float f0[4], f1[4];
        #pragma unroll
        for (int h = 0; h < 4; h++) { f0[h] = r0[h * C1]; f1[h] = r1[h * C1]; }
        float as0a[4] = {as0.x, as0.y, as0.z, as0.w};
        float as1a[4] = {as1.x, as1.y, as1.z, as1.w};
        #pragma unroll
        for (int h = 0; h < 4; h++) {
            float e0 = as0a[h] + ad[h]; e0 = e0 > 0.f ? e0 : NEG_SLOPE * e0;
            float e1 = as1a[h] + ad[h]; e1 = e1 > 0.f ? e1 : NEG_SLOPE * e1;
            float x0 = __expf(e0 - m[h]);
            float x1 = __expf(e1 - m[h]);
            ssum[h] += x0 + x1;
            acc[h] = fmaf(x0, f0[h], fmaf(x1, f1[h], acc[h]));
        }
    }
    if (i < end) {
        int s = g_srcs[i];
        float4 as4 = *(const float4*)&g_a1s[s * H1 + hb];
        const float* r = &g_h1[(size_t)s * D1 + hb * C1 + lane];
        float asa[4] = {as4.x, as4.y, as4.z, as4.w};
        #pragma unroll
        for (int h = 0; h < 4; h++) {
            float e = asa[h] + ad[h]; e = e > 0.f ? e : NEG_SLOPE * e;
            float x = __expf(e - m[h]);
            ssum[h] += x;
            acc[h] = fmaf(x, r[h * C1], acc[h]);
        }
    }
    float* orow = &g_out1[(size_t)d * D1 + hb * C1 + lane];
    #pragma unroll
    for (int h = 0; h < 4; h++) {
        float o = acc[h] / (ssum[h] + EPS) + __ldg(&b1[(hb + h) * C1 + lane]);
        o = o > 0.0f ? o : expm1f(o);  // elu
        orow[h * C1] = o;
    }
}

// ---------------- layer 2 attention logits (1 head, 64 ch) ------------------
__global__ void att2_kernel(const float* __restrict__ att_s,
                            const float* __restrict__ att_d, int N) {
    int warp = (blockIdx.x * blockDim.x + threadIdx.x) >> 5;
    int lane = threadIdx.x & 31;
    if (warp >= N) return;
    int n = warp;
    float v0 = g_h2[(size_t)n * D2 + lane];
    float v1 = g_h2[(size_t)n * D2 + 32 + lane];
    float ps = v0 * __ldg(&att_s[lane]) + v1 * __ldg(&att_s[32 + lane]);
    float pd = v0 * __ldg(&att_d[lane]) + v1 * __ldg(&att_d[32 + lane]);
    #pragma unroll
    for (int o = 16; o > 0; o >>= 1) {
        ps += __shfl_xor_sync(0xffffffffu, ps, o);
        pd += __shfl_xor_sync(0xffffffffu, pd, o);
    }
    if (lane == 0) { g_a2s[n] = ps; g_a2d[n] = pd; }
}

// ---------------- layer 2 aggregation: warp per dst, unroll 2 ---------------
__global__ void agg2_kernel(const float* __restrict__ b2,
                            float* __restrict__ out, int N) {
    int warp = (blockIdx.x * blockDim.x + threadIdx.x) >> 5;
    int lane = threadIdx.x & 31;
    if (warp >= N) return;
    int d = warp;
    int beg = g_offs[d], end = g_offs[d + 1];
    float ad = g_a2d[d];

    float m = -CUDART_INF_F;
    for (int i = beg + lane; i < end; i += 32) {
        int s = g_srcs[i];
        float e = g_a2s[s] + ad;
        e = e > 0.0f ? e : NEG_SLOPE * e;
        m = fmaxf(m, e);
    }
    #pragma unroll
    for (int o = 16; o > 0; o >>= 1)
        m = fmaxf(m, __shfl_xor_sync(0xffffffffu, m, o));

    float acc0 = 0.0f, acc1 = 0.0f, ssum = 0.0f;
    int i = beg;
    for (; i + 1 < end; i += 2) {
        int s0 = g_srcs[i], s1 = g_srcs[i + 1];
        float e0 = g_a2s[s0] + ad; e0 = e0 > 0.f ? e0 : NEG_SLOPE * e0;
        float e1 = g_a2s[s1] + ad; e1 = e1 > 0.f ? e1 : NEG_SLOPE * e1;
        const float* r0 = &g_h2[(size_t)s0 * D2];
        const float* r1 = &g_h2[(size_t)s1 * D2];
        float fa0 = r0[lane], fb0 = r0[32 + lane];
        float fa1 = r1[lane], fb1 = r1[32 + lane];
        float x0 = __expf(e0 - m);
        float x1 = __expf(e1 - m);
        ssum += x0 + x1;
        acc0 = fmaf(x0, fa0, fmaf(x1, fa1, acc0));
        acc1 = fmaf(x0, fb0, fmaf(x1, fb1, acc1));
    }
    if (i < end) {
        int s = g_srcs[i];
        float e = g_a2s[s] + ad;
        e = e > 0.0f ? e : NEG_SLOPE * e;
        float x = __expf(e - m);
        ssum += x;
        const float* r = &g_h2[(size_t)s * D2];
        acc0 = fmaf(x, r[lane],      acc0);
        acc1 = fmaf(x, r[32 + lane], acc1);
    }
    float inv = 1.0f / (ssum + EPS);
    out[(size_t)d * D2 + lane]      = acc0 * inv + __ldg(&b2[lane]);
    out[(size_t)d * D2 + 32 + lane] = acc1 * inv + __ldg(&b2[32 + lane]);
}

// ---------------- launch ----------------------------------------------------
extern "C" void kernel_launch(void* const* d_in, const int* in_sizes, int n_in,
                              void* d_out, int out_size) {
    const float* x    = (const float*)d_in[0];
    const unsigned int* edge_w = (const unsigned int*)d_in[1];
    const float* W1   = (const float*)d_in[2];
    const float* as1  = (const float*)d_in[3];
    const float* ad1  = (const float*)d_in[4];
    const float* b1   = (const float*)d_in[5];
    const float* W2   = (const float*)d_in[6];
    const float* as2  = (const float*)d_in[7];
    const float* ad2  = (const float*)d_in[8];
    const float* b2   = (const float*)d_in[9];
    float* out = (float*)d_out;

    int N = in_sizes[0] / IN1;
    int E = in_sizes[1] / 2;

    int nb = (N + 255) / 256;

    // dtype probe + CSR build (self loops folded in)
    detect_kernel<<<1, 256>>>(edge_w, 2 * E);
    init_cnt_kernel<<<nb, 256>>>(N);
    normalize_hist_kernel<<<(E + 255) / 256, 256>>>(edge_w, E, N);
    scan_block_kernel<<<nb, 256>>>(N);
    scan_top_kernel<<<1, 256>>>(nb);
    scan_add_kernel<<<nb, 256>>>(N);
    scatter_self_kernel<<<nb, 256>>>(N);
    scatter_edge_kernel<<<(E + 255) / 256, 256>>>(E, N);

    // layer 1
    dim3 g1((N + 127) / 128, D1 / 64);
    gemm_tf32_kernel<<<g1, 256>>>(x, W1, /*which=*/0, N, IN1, D1);
    att1_kernel<<<N, 256>>>(as1, ad1, N);
    agg1_kernel<<<(2 * N + 7) / 8, 256>>>(b1, N);   // 2 warps per dst

    // layer 2
    dim3 g2((N + 127) / 128, D2 / 64);
    gemm_tf32_kernel<<<g2, 256>>>(x /*unused*/, W2, /*which=*/1, N, D1, D2);
    att2_kernel<<<(N + 7) / 8, 256>>>(as2, ad2, N);
    agg2_kernel<<<(N + 7) / 8, 256>>>(b2, out, N);
}